// round 1
// baseline (speedup 1.0000x reference)
#include <cuda_runtime.h>

// 8-bit ripple adder on {0,1}-valued float32 inputs.
// A, B: [N, 8] MSB-first; Cin: [N, 1].
// Output: sums [N, 8] followed by carry [N, 1] (flattened, return order).
//
// Since inputs are exactly 0.0f / 1.0f, the differentiable full-adder chain
// is exactly an 8-bit integer add: pack bits -> s = a + b + cin -> unpack.

__global__ void adder8_kernel(const float4* __restrict__ A,
                              const float4* __restrict__ B,
                              const float*  __restrict__ Cin,
                              float4* __restrict__ Sums,
                              float*  __restrict__ Carry,
                              int N, int write_carry)
{
    int r = blockIdx.x * blockDim.x + threadIdx.x;
    if (r >= N) return;

    // Each row = two float4 (8 floats), MSB first.
    float4 a0 = A[2 * r + 0];
    float4 a1 = A[2 * r + 1];
    float4 b0 = B[2 * r + 0];
    float4 b1 = B[2 * r + 1];
    float  c  = Cin[r];

    // Pack MSB-first bits into an integer (A[...,0] has weight 128).
    unsigned av =
        ((a0.x > 0.5f) ? 128u : 0u) | ((a0.y > 0.5f) ? 64u : 0u) |
        ((a0.z > 0.5f) ? 32u  : 0u) | ((a0.w > 0.5f) ? 16u : 0u) |
        ((a1.x > 0.5f) ? 8u   : 0u) | ((a1.y > 0.5f) ? 4u  : 0u) |
        ((a1.z > 0.5f) ? 2u   : 0u) | ((a1.w > 0.5f) ? 1u  : 0u);
    unsigned bv =
        ((b0.x > 0.5f) ? 128u : 0u) | ((b0.y > 0.5f) ? 64u : 0u) |
        ((b0.z > 0.5f) ? 32u  : 0u) | ((b0.w > 0.5f) ? 16u : 0u) |
        ((b1.x > 0.5f) ? 8u   : 0u) | ((b1.y > 0.5f) ? 4u  : 0u) |
        ((b1.z > 0.5f) ? 2u   : 0u) | ((b1.w > 0.5f) ? 1u  : 0u);
    unsigned cv = (c > 0.5f) ? 1u : 0u;

    unsigned s = av + bv + cv;   // 9-bit result

    float4 s0, s1;
    s0.x = (float)((s >> 7) & 1u);   // sums[0] = MSB (bit 7)
    s0.y = (float)((s >> 6) & 1u);
    s0.z = (float)((s >> 5) & 1u);
    s0.w = (float)((s >> 4) & 1u);
    s1.x = (float)((s >> 3) & 1u);
    s1.y = (float)((s >> 2) & 1u);
    s1.z = (float)((s >> 1) & 1u);
    s1.w = (float)( s        & 1u);  // sums[7] = LSB

    Sums[2 * r + 0] = s0;
    Sums[2 * r + 1] = s1;
    if (write_carry)
        Carry[r] = (float)((s >> 8) & 1u);
}

extern "C" void kernel_launch(void* const* d_in, const int* in_sizes, int n_in,
                              void* d_out, int out_size)
{
    const float4* A   = (const float4*)d_in[0];
    const float4* B   = (const float4*)d_in[1];
    const float*  Cin = (const float*)d_in[2];

    int N = in_sizes[0] / 8;   // [N, 8]

    float* out   = (float*)d_out;
    float4* Sums = (float4*)out;
    float*  Carry = out + (size_t)8 * N;

    // Defensive: if the harness only exposes the sums (out_size == 8N),
    // skip the carry writes to avoid OOB.
    int write_carry = (out_size >= 9 * N) ? 1 : 0;

    const int threads = 256;
    int blocks = (N + threads - 1) / threads;
    adder8_kernel<<<blocks, threads>>>(A, B, Cin, Sums, Carry, N, write_carry);
}